// round 11
// baseline (speedup 1.0000x reference)
#include <cuda_runtime.h>

#define LEN     262144
#define NFFT    1024
#define STRIDE  256
#define HALF    512
#define CUT     513
#define NFRM    1029
#define NB      32
#define PLANE   16892064u    // 32*513*1029
#define TB      4            // frames per block
#define FROW    1160         // fbuf row stride in floats (8-bank offset per frame)

// DP-accurate tables in global memory (small, L1/L2-hot)
__device__ float2 g_tw[CUT];      // W_1024^j, j=0..512 (untangle)
__device__ float2 g_win2[HALF];   // Hann pairs (2j, 2j+1)
__device__ float2 g_T1[8 * 64];   // [ka][l]  = W_512^{l*ka}
__device__ float2 g_T2[8 * 8];    // [kc][n0] = W_64^{n0*kc}

__global__ void init_tables() {
    int j = blockIdx.x * blockDim.x + threadIdx.x;
    if (j < CUT) {
        double s, c;
        sincospi(-(double)j / 512.0, &s, &c);
        float2 w = make_float2((float)c, (float)s);
        if (j == 512) w = make_float2(-1.0f, 0.0f);  // pin: Xi[512] exactly +0
        if (j == 0)   w = make_float2( 1.0f, 0.0f);
        if (j == 256) w = make_float2( 0.0f, -1.0f);
        g_tw[j] = w;
    }
    if (j < HALF) {
        double s0, c0, s1, c1;
        sincospi(2.0 * (double)(2*j)     / (double)NFFT, &s0, &c0);
        sincospi(2.0 * (double)(2*j + 1) / (double)NFFT, &s1, &c1);
        g_win2[j] = make_float2((float)(0.5 - 0.5*c0), (float)(0.5 - 0.5*c1));
    }
    if (j < 8 * 64) {
        int ka = j >> 6, l = j & 63;
        double s, c;
        sincospi(-(double)(l * ka) / 256.0, &s, &c);   // W_512^{l*ka}
        g_T1[j] = make_float2((float)c, (float)s);
    }
    if (j < 8 * 8) {
        int kc = j >> 3, n0 = j & 7;
        double s, c;
        sincospi(-(double)(n0 * kc) / 32.0, &s, &c);   // W_64^{n0*kc}
        g_T2[j] = make_float2((float)c, (float)s);
    }
}

__device__ __forceinline__ float2 cmul(float2 a, float2 b) {
    return make_float2(fmaf(a.x, b.x, -a.y*b.y), fmaf(a.x, b.y, a.y*b.x));
}
__device__ __forceinline__ float2 cadd(float2 a, float2 b) { return make_float2(a.x+b.x, a.y+b.y); }
__device__ __forceinline__ float2 csub(float2 a, float2 b) { return make_float2(a.x-b.x, a.y-b.y); }

// Fast atan2 (max abs err ~1e-7 rad). Edge cases match numpy:
// atan2(±0,+0)=±0, atan2(±0,neg)=±pi, atan2(0,0)=0.
__device__ __forceinline__ float fast_atan2f(float y, float x) {
    float ax = fabsf(x), ay = fabsf(y);
    float mx = fmaxf(ax, ay), mn = fminf(ax, ay);
    float t = (mx > 0.f) ? __fdividef(mn, mx) : 0.f;   // [0,1]
    float s = t * t;
    float p =           -0.0040540580f;
    p = fmaf(p, s,       0.0218612288f);
    p = fmaf(p, s,      -0.0559098861f);
    p = fmaf(p, s,       0.0964200441f);
    p = fmaf(p, s,      -0.1390853351f);
    p = fmaf(p, s,       0.1994653599f);
    p = fmaf(p, s,      -0.3332985605f);
    p = fmaf(p, s,       0.9999993329f);
    float r = p * t;
    if (ay > ax)  r = 1.57079632679489662f - r;
    if (x < 0.f)  r = 3.14159265358979324f - r;
    return copysignf(r, y);
}

__device__ __forceinline__ float fast_sqrtf(float a) {
    float r;
    asm("sqrt.approx.f32 %0, %1;" : "=f"(r) : "f"(a));
    return r;
}

// y[r] = sum_j a[j] * W8^{j*r}
__device__ __forceinline__ void dft8(const float2 a[8], float2 y[8]) {
    float2 e0 = cadd(a[0], a[4]), e1 = csub(a[0], a[4]);
    float2 f0 = cadd(a[2], a[6]), f1 = csub(a[2], a[6]);
    float2 g0 = cadd(a[1], a[5]), g1 = csub(a[1], a[5]);
    float2 h0 = cadd(a[3], a[7]), h1 = csub(a[3], a[7]);
    float2 E0 = cadd(e0, f0), E2 = csub(e0, f0);
    float2 E1 = make_float2(e1.x + f1.y, e1.y - f1.x);   // e1 - i*f1
    float2 E3 = make_float2(e1.x - f1.y, e1.y + f1.x);   // e1 + i*f1
    float2 O0 = cadd(g0, h0), O2 = csub(g0, h0);
    float2 O1 = make_float2(g1.x + h1.y, g1.y - h1.x);
    float2 O3 = make_float2(g1.x - h1.y, g1.y + h1.x);
    const float C = 0.70710678118654752440f;
    float2 t1 = make_float2(C*(O1.x + O1.y), C*(O1.y - O1.x));    // W8^1*O1
    float2 t2 = make_float2(O2.y, -O2.x);                          // -i*O2
    float2 t3 = make_float2(C*(O3.y - O3.x), -C*(O3.x + O3.y));   // W8^3*O3
    y[0] = cadd(E0, O0); y[4] = csub(E0, O0);
    y[1] = cadd(E1, t1); y[5] = csub(E1, t1);
    y[2] = cadd(E2, t2); y[6] = csub(E2, t2);
    y[3] = cadd(E3, t3); y[7] = csub(E3, t3);
}

// 256 threads = 4 frames x 64 lanes. Register radix-8^3 FFT, scalar
// conflict-free smem exchanges. Untangle fused into the store phase.
__global__ __launch_bounds__(256) void stft_kernel(const float* __restrict__ x,
                                                   float* __restrict__ out) {
    __shared__ float2 tw[CUT];            // 4104 B
    __shared__ float  fbuf[TB][FROW];     // 4 x 4640 B (exchanges / Z planes, aliased)

    const int tid = threadIdx.x;
    const int f   = tid >> 6;        // frame within block
    const int l   = tid & 63;        // lane within frame
    const int t0  = blockIdx.x * TB;
    const int b   = blockIdx.y;
    const int t   = t0 + f;

    for (int r = tid; r < CUT; r += 256) tw[r] = g_tw[r];

    float*  base = fbuf[f];
    float2* b2   = (float2*)base;

    // ---- Pass 1: load (global->regs, windowed, packed), radix-8 over n2 ----
    const float* xb = x + (size_t)b * LEN;
    const int start = t * STRIDE - NFFT;      // always even
    float2 a[8], y[8];
    #pragma unroll
    for (int j = 0; j < 8; j++) {
        int n  = l + 64 * j;                  // packed complex index
        int i0 = start + 2 * n;
        float2 v = make_float2(0.f, 0.f);
        if (i0 >= 0 && i0 < LEN) v = *(const float2*)(xb + i0);
        float2 w = g_win2[n];
        a[j] = make_float2(v.x * w.x, v.y * w.y);
    }
    dft8(a, y);
    #pragma unroll
    for (int ka = 1; ka < 8; ka++) y[ka] = cmul(y[ka], g_T1[ka * 64 + l]);
    {   // exchange 1 write: idx = 72*n1 + n0 + 8*ka  (conflict-free)
        int n0 = l & 7, n1 = l >> 3;
        #pragma unroll
        for (int ka = 0; ka < 8; ka++) b2[72 * n1 + n0 + 8 * ka] = y[ka];
    }
    __syncthreads();

    // ---- Pass 2: thread (n0, ka), radix-8 over n1 ----
    {
        int n0 = l & 7, ka = l >> 3;
        #pragma unroll
        for (int n1 = 0; n1 < 8; n1++) a[n1] = b2[72 * n1 + n0 + 8 * ka];
        dft8(a, y);
        #pragma unroll
        for (int kc = 1; kc < 8; kc++) y[kc] = cmul(y[kc], g_T2[kc * 8 + n0]);
        __syncthreads();   // reads complete before aliased overwrite
        #pragma unroll
        for (int kc = 0; kc < 8; kc++) b2[65 * n0 + kc + 8 * ka] = y[kc];
    }
    __syncthreads();

    // ---- Pass 3: thread (kc, ka), radix-8 over n0; Z[ka + 8kc + 64kd] ----
    {
        int kc = l & 7, ka = l >> 3;
        #pragma unroll
        for (int n0 = 0; n0 < 8; n0++) a[n0] = b2[65 * n0 + kc + 8 * ka];
        dft8(a, y);
        __syncthreads();   // reads complete before aliased Z write
        float* zre = base;
        float* zim = base + 576;
        #pragma unroll
        for (int kd = 0; kd < 8; kd++) {
            int k  = ka + 8 * kc + 64 * kd;
            int zi = k + 4 * (k >> 5);        // conflict-free scalar layout
            zre[zi] = y[kd].x;
            zim[zi] = y[kd].y;
        }
    }
    __syncthreads();

    // ---- Fused untangle + mag/angle + store (32-bit indexing) ----
    // Thread (k0 = tid>>2, ff = tid&3): k = k0 + 64*r, frame ff.
    // fbuf rows skewed by 8 banks per frame -> conflict-free cross-frame reads.
    {
        float* __restrict__ mag_out = out;
        float* __restrict__ ang_out = out + PLANE;
        const int k0 = tid >> 2;
        const int ff = tid & 3;
        const float* zre = fbuf[ff];
        const float* zim = fbuf[ff] + 576;
        if (t0 + ff < NFRM) {
            unsigned o = (unsigned)(b * CUT + k0) * NFRM + (unsigned)(t0 + ff);
            #pragma unroll
            for (int r = 0; r < 8; r++) {      // k = k0+64r <= 511 always
                int k  = k0 + 64 * r;
                int i2 = (512 - k) & 511;
                int z1 = k  + 4 * (k  >> 5);
                int z2 = i2 + 4 * (i2 >> 5);
                float Ax = zre[z1], Ay = zim[z1];
                float Bx = zre[z2], By = -zim[z2];
                float2 w = tw[k];
                float sr = Ax + Bx, si = Ay + By;
                float dr = Ax - Bx, di = Ay - By;
                float Xr = 0.5f * (sr + fmaf(w.x, di,  w.y * dr));
                float Xi = 0.5f * (si - fmaf(w.x, dr, -w.y * di));
                mag_out[o] = fast_sqrtf(fmaf(Xr, Xr, Xi * Xi));
                ang_out[o] = fast_atan2f(Xi, Xr);
                o += 64u * NFRM;
            }
            if (k0 == 0) {                     // k = 512 tail (4 threads)
                const int k = 512;
                int z1 = 0 + 4 * 0;            // i1 = 0
                float Ax = zre[z1], Ay = zim[z1];
                // B = conj(Z[0]) -> sr=2Ax, si=0, dr=0, di=2Ay; w=(-1,0)
                float Xr = 0.5f * (2.f*Ax + (-1.f) * (2.f*Ay) * 0.f);  // = Ax
                float Xi = 0.0f;                // exact by w=(−1,0) pin
                Xr = Ax - 0.f;                  // X[512] = Re(Z0) - ... simplified below
                // Full formula with w=(-1,0): Xr = 0.5*(sr + w.x*di) = Ax - Ay... careful:
                // sr=2Ax, di=2Ay, w.x=-1, w.y=0:
                Xr = 0.5f * (2.f*Ax + (-1.f)*(2.f*Ay));   // Ax - Ay
                Xi = 0.5f * (0.f - ((-1.f)*0.f - 0.f));   // +0 exactly
                unsigned o = (unsigned)(b * CUT + k) * NFRM + (unsigned)(t0 + ff);
                mag_out[o] = fast_sqrtf(Xr * Xr);
                ang_out[o] = fast_atan2f(Xi, Xr);
            }
        }
    }
}

extern "C" void kernel_launch(void* const* d_in, const int* in_sizes, int n_in,
                              void* d_out, int out_size) {
    const float* x = (const float*)d_in[0];   // (32, 1, 262144) fp32
    float* out = (float*)d_out;               // mag plane then angle plane
    init_tables<<<(NFFT + 127) / 128, 128>>>();
    dim3 grid((NFRM + TB - 1) / TB, NB);      // 258 x 32
    stft_kernel<<<grid, 256>>>(x, out);
}

// round 12
// speedup vs baseline: 1.0870x; 1.0870x over previous
#include <cuda_runtime.h>

#define LEN     262144
#define NFFT    1024
#define STRIDE  256
#define HALF    512
#define CUT     513
#define NFRM    1029
#define NB      32
#define PLANE   16892064u    // 32*513*1029
#define TB      8            // frames per block
#define FROW    1156         // fbuf row stride in floats (== 4 banks mod 32)

// DP-accurate tables in global memory (small, L1/L2-hot)
__device__ float2 g_tw[CUT];      // W_1024^j, j=0..512 (untangle)
__device__ float2 g_win2[HALF];   // Hann pairs (2j, 2j+1)
__device__ float2 g_T1[8 * 64];   // [ka][l]  = W_512^{l*ka}
__device__ float2 g_T2[8 * 8];    // [kc][n0] = W_64^{n0*kc}

__global__ void init_tables() {
    int j = blockIdx.x * blockDim.x + threadIdx.x;
    if (j < CUT) {
        double s, c;
        sincospi(-(double)j / 512.0, &s, &c);
        float2 w = make_float2((float)c, (float)s);
        if (j == 512) w = make_float2(-1.0f, 0.0f);  // pin: Xi[512] exactly +0
        if (j == 0)   w = make_float2( 1.0f, 0.0f);
        if (j == 256) w = make_float2( 0.0f, -1.0f);
        g_tw[j] = w;
    }
    if (j < HALF) {
        double s0, c0, s1, c1;
        sincospi(2.0 * (double)(2*j)     / (double)NFFT, &s0, &c0);
        sincospi(2.0 * (double)(2*j + 1) / (double)NFFT, &s1, &c1);
        g_win2[j] = make_float2((float)(0.5 - 0.5*c0), (float)(0.5 - 0.5*c1));
    }
    if (j < 8 * 64) {
        int ka = j >> 6, l = j & 63;
        double s, c;
        sincospi(-(double)(l * ka) / 256.0, &s, &c);   // W_512^{l*ka}
        g_T1[j] = make_float2((float)c, (float)s);
    }
    if (j < 8 * 8) {
        int kc = j >> 3, n0 = j & 7;
        double s, c;
        sincospi(-(double)(n0 * kc) / 32.0, &s, &c);   // W_64^{n0*kc}
        g_T2[j] = make_float2((float)c, (float)s);
    }
}

__device__ __forceinline__ float2 cmul(float2 a, float2 b) {
    return make_float2(fmaf(a.x, b.x, -a.y*b.y), fmaf(a.x, b.y, a.y*b.x));
}
__device__ __forceinline__ float2 cadd(float2 a, float2 b) { return make_float2(a.x+b.x, a.y+b.y); }
__device__ __forceinline__ float2 csub(float2 a, float2 b) { return make_float2(a.x-b.x, a.y-b.y); }

// Fast atan2 (max abs err ~1e-7 rad). Edge cases match numpy.
__device__ __forceinline__ float fast_atan2f(float y, float x) {
    float ax = fabsf(x), ay = fabsf(y);
    float mx = fmaxf(ax, ay), mn = fminf(ax, ay);
    float t = (mx > 0.f) ? __fdividef(mn, mx) : 0.f;   // [0,1]
    float s = t * t;
    float p =           -0.0040540580f;
    p = fmaf(p, s,       0.0218612288f);
    p = fmaf(p, s,      -0.0559098861f);
    p = fmaf(p, s,       0.0964200441f);
    p = fmaf(p, s,      -0.1390853351f);
    p = fmaf(p, s,       0.1994653599f);
    p = fmaf(p, s,      -0.3332985605f);
    p = fmaf(p, s,       0.9999993329f);
    float r = p * t;
    if (ay > ax)  r = 1.57079632679489662f - r;
    if (x < 0.f)  r = 3.14159265358979324f - r;
    return copysignf(r, y);
}

__device__ __forceinline__ float fast_sqrtf(float a) {
    float r;
    asm("sqrt.approx.f32 %0, %1;" : "=f"(r) : "f"(a));
    return r;
}

// y[r] = sum_j a[j] * W8^{j*r}
__device__ __forceinline__ void dft8(const float2 a[8], float2 y[8]) {
    float2 e0 = cadd(a[0], a[4]), e1 = csub(a[0], a[4]);
    float2 f0 = cadd(a[2], a[6]), f1 = csub(a[2], a[6]);
    float2 g0 = cadd(a[1], a[5]), g1 = csub(a[1], a[5]);
    float2 h0 = cadd(a[3], a[7]), h1 = csub(a[3], a[7]);
    float2 E0 = cadd(e0, f0), E2 = csub(e0, f0);
    float2 E1 = make_float2(e1.x + f1.y, e1.y - f1.x);   // e1 - i*f1
    float2 E3 = make_float2(e1.x - f1.y, e1.y + f1.x);   // e1 + i*f1
    float2 O0 = cadd(g0, h0), O2 = csub(g0, h0);
    float2 O1 = make_float2(g1.x + h1.y, g1.y - h1.x);
    float2 O3 = make_float2(g1.x - h1.y, g1.y + h1.x);
    const float C = 0.70710678118654752440f;
    float2 t1 = make_float2(C*(O1.x + O1.y), C*(O1.y - O1.x));    // W8^1*O1
    float2 t2 = make_float2(O2.y, -O2.x);                          // -i*O2
    float2 t3 = make_float2(C*(O3.y - O3.x), -C*(O3.x + O3.y));   // W8^3*O3
    y[0] = cadd(E0, O0); y[4] = csub(E0, O0);
    y[1] = cadd(E1, t1); y[5] = csub(E1, t1);
    y[2] = cadd(E2, t2); y[6] = csub(E2, t2);
    y[3] = cadd(E3, t3); y[7] = csub(E3, t3);
}

// 512 threads = 8 frames x 64 lanes. Register radix-8^3 FFT, scalar
// conflict-free smem exchanges. Conjugate-paired untangle fused into the
// store phase; stores hit full 32B sectors (8 contiguous t).
__global__ __launch_bounds__(512) void stft_kernel(const float* __restrict__ x,
                                                   float* __restrict__ out) {
    __shared__ float2 tw[CUT];            // 4104 B
    __shared__ float  fbuf[TB][FROW];     // 8 x 4624 B (exchanges / Z planes, aliased)

    const int tid = threadIdx.x;
    const int f   = tid >> 6;        // frame within block (0..7)
    const int l   = tid & 63;        // lane within frame
    const int t0  = blockIdx.x * TB;
    const int b   = blockIdx.y;
    const int t   = t0 + f;

    for (int r = tid; r < CUT; r += 512) tw[r] = g_tw[r];

    float*  base = fbuf[f];
    float2* b2   = (float2*)base;

    // ---- Pass 1: load (global->regs, windowed, packed), radix-8 over n2 ----
    const float* xb = x + (size_t)b * LEN;
    const int start = t * STRIDE - NFFT;      // always even
    float2 a[8], y[8];
    #pragma unroll
    for (int j = 0; j < 8; j++) {
        int n  = l + 64 * j;                  // packed complex index
        int i0 = start + 2 * n;
        float2 v = make_float2(0.f, 0.f);
        if (i0 >= 0 && i0 < LEN) v = *(const float2*)(xb + i0);
        float2 w = g_win2[n];
        a[j] = make_float2(v.x * w.x, v.y * w.y);
    }
    dft8(a, y);
    #pragma unroll
    for (int ka = 1; ka < 8; ka++) y[ka] = cmul(y[ka], g_T1[ka * 64 + l]);
    {   // exchange 1 write: idx = 72*n1 + n0 + 8*ka  (conflict-free)
        int n0 = l & 7, n1 = l >> 3;
        #pragma unroll
        for (int ka = 0; ka < 8; ka++) b2[72 * n1 + n0 + 8 * ka] = y[ka];
    }
    __syncthreads();

    // ---- Pass 2: thread (n0, ka), radix-8 over n1 ----
    {
        int n0 = l & 7, ka = l >> 3;
        #pragma unroll
        for (int n1 = 0; n1 < 8; n1++) a[n1] = b2[72 * n1 + n0 + 8 * ka];
        dft8(a, y);
        #pragma unroll
        for (int kc = 1; kc < 8; kc++) y[kc] = cmul(y[kc], g_T2[kc * 8 + n0]);
        __syncthreads();   // reads complete before aliased overwrite
        #pragma unroll
        for (int kc = 0; kc < 8; kc++) b2[65 * n0 + kc + 8 * ka] = y[kc];
    }
    __syncthreads();

    // ---- Pass 3: thread (kc, ka), radix-8 over n0; Z[ka + 8kc + 64kd] ----
    {
        int kc = l & 7, ka = l >> 3;
        #pragma unroll
        for (int n0 = 0; n0 < 8; n0++) a[n0] = b2[65 * n0 + kc + 8 * ka];
        dft8(a, y);
        __syncthreads();   // reads complete before aliased Z write
        float* zre = base;
        float* zim = base + 576;
        #pragma unroll
        for (int kd = 0; kd < 8; kd++) {
            int k  = ka + 8 * kc + 64 * kd;
            int zi = k + 4 * (k >> 5);        // conflict-free scalar layout
            zre[zi] = y[kd].x;
            zim[zi] = y[kd].y;
        }
    }
    __syncthreads();

    // ---- Fused conjugate-paired untangle + mag/angle + store ----
    // Thread (k0 = tid>>3, ff = tid&7): handles k = k0+64r (r<4, k<256) AND
    // its pair 512-k from the same Z reads. Stores: 8 contiguous t per k row
    // (full 32B sectors). fbuf row stride == 4 banks mod 32 -> conflict-free.
    {
        float* __restrict__ mag_out = out;
        float* __restrict__ ang_out = out + PLANE;
        const int k0 = tid >> 3;        // 0..63
        const int ff = tid & 7;
        const float* zre = fbuf[ff];
        const float* zim = fbuf[ff] + 576;
        if (t0 + ff < NFRM) {
            unsigned o1 = (unsigned)(b * CUT + k0)        * NFRM + (unsigned)(t0 + ff);
            unsigned o2 = (unsigned)(b * CUT + (512 - k0))* NFRM + (unsigned)(t0 + ff);
            #pragma unroll
            for (int r = 0; r < 4; r++) {
                int k  = k0 + 64 * r;          // [0, 256)
                int i2 = (512 - k) & 511;
                int z1 = k  + 4 * (k  >> 5);
                int z2 = i2 + 4 * (i2 >> 5);
                float Ax = zre[z1], Ay = zim[z1];
                float Bx = zre[z2], By = -zim[z2];
                float2 w = tw[k];
                float sr = Ax + Bx, si = Ay + By;
                float dr = Ax - Bx, di = Ay - By;
                float Xr = 0.5f * (sr + fmaf(w.x, di,  w.y * dr));
                float Xi = 0.5f * (si - fmaf(w.x, dr, -w.y * di));
                mag_out[o1] = fast_sqrtf(fmaf(Xr, Xr, Xi * Xi));
                ang_out[o1] = fast_atan2f(Xi, Xr);
                float Yr = sr - Xr;            // X[512-k] via conjugate pairing
                float Yi = Xi - si;
                mag_out[o2] = fast_sqrtf(fmaf(Yr, Yr, Yi * Yi));
                ang_out[o2] = fast_atan2f(Yi, Yr);
                o1 += 64u * NFRM;
                o2 -= 64u * NFRM;
            }
            if (k0 == 0) {                     // self-paired bin k = 256
                float Ax = zre[288], Ay = zim[288];    // z(256) = 256 + 4*8
                unsigned o = (unsigned)(b * CUT + 256) * NFRM + (unsigned)(t0 + ff);
                mag_out[o] = fast_sqrtf(fmaf(Ax, Ax, Ay * Ay));
                ang_out[o] = fast_atan2f(-Ay, Ax);     // X[256] = conj(Z[256])
            }
        }
    }
}

extern "C" void kernel_launch(void* const* d_in, const int* in_sizes, int n_in,
                              void* d_out, int out_size) {
    const float* x = (const float*)d_in[0];   // (32, 1, 262144) fp32
    float* out = (float*)d_out;               // mag plane then angle plane
    init_tables<<<(NFFT + 127) / 128, 128>>>();
    dim3 grid((NFRM + TB - 1) / TB, NB);      // 129 x 32
    stft_kernel<<<grid, 512>>>(x, out);
}